// round 15
// baseline (speedup 1.0000x reference)
#include <cuda_runtime.h>
#include <cuda_fp16.h>
#include <math_constants.h>
#include <cstdint>

// Round 15: two-kernel pipeline.
//  - maskconv_kernel: threefry keep-words (bit-identical layout) + fp32->fp16
//    conversion folded in (DRAM pass hides under the ALU wall; convert kernel
//    deleted).
//  - attn: BN 64->128 (16 k-iterations): halves barriers, oacc rescales,
//    shuffle reductions, per-tile overhead. Same MMA/ldsm totals, same math
//    (1-pass qh@kh, fp16 PV). smem 102KB -> still 2 CTAs/SM.
// rel_err ~7.1e-4 (R14-calibrated; softmax block order shifts rounding only).

#define S_LEN 2048
#define D_DIM 128
#define BM 64
#define BN 128
#define NT 128
#define NELEM (2 * 16 * S_LEN * D_DIM)
#define NMASKW (1 << 22)

#define KTILE_B (128 * 272)             // K tile: 128 rows x 272 B = 34816
#define OFF_K0 0
#define OFF_K1 KTILE_B                  // 34816
#define OFF_V  (2 * KTILE_B)            // 69632
#define SMEM_BYTES (3 * KTILE_B)        // 104448 -> 2 CTAs/SM (208896 <= 227KB)

__device__ __half g_Kh[NELEM];
__device__ __half g_Vh[NELEM];
__device__ uint32_t g_mask[NMASKW];

// ---------------- threefry (JAX partitionable, key=(0,42)), trimmed ----------------
__device__ __forceinline__ unsigned tf_rotl(unsigned x, int r) {
    return __funnelshift_l(x, x, r);
}
__device__ __forceinline__ unsigned threefry_keep_msb(unsigned g) {
    const unsigned ks1 = 42u;
    const unsigned ks2 = 0x1BD11BDAu ^ 42u;
    unsigned x0 = 0u;
    unsigned x1 = g + ks1;
#define TF_R(r)            { x0 += x1; x1 = tf_rotl(x1, (r)) ^ x0; }
#define TF_IR(ka, kb, r)   { x1 += (kb); x0 = x0 + (ka) + x1; x1 = tf_rotl(x1, (r)) ^ x0; }
    TF_R(13) TF_R(15) TF_R(26) TF_R(6)
    TF_IR(ks1, ks2 + 1u, 17) TF_R(29) TF_R(16) TF_R(24)
    TF_IR(ks2, 2u,       13) TF_R(15) TF_R(26) TF_R(6)
    TF_IR(0u,  ks1 + 3u, 17) TF_R(29) TF_R(16) TF_R(24)
    TF_IR(ks1, ks2 + 4u, 13) TF_R(15) TF_R(26) TF_R(6)
#undef TF_R
#undef TF_IR
    return ~((x0 + ks2) ^ (x1 + 5u));   // XNOR: MSB==1 iff KEEP
}

// ---------------- fused mask + convert kernel ----------------
// mask word layout identical to R14 (BM=64 fragment indexing):
//   idx = ((((bh*32 + qtile)*4 + warp)*32 + kt64)*32 + lane
// convert: first NELEM/8 threads each convert one float4-pair (K and V).
__global__ void __launch_bounds__(256)
maskconv_kernel(const float* __restrict__ x1, const float* __restrict__ x2)
{
    unsigned idx = blockIdx.x * 256u + threadIdx.x;

    // -- folded conversion (issues loads early; hides under threefry ALU) --
    if (idx < (unsigned)(NELEM / 4)) {
        float4 k = reinterpret_cast<const float4*>(x2)[idx];
        float4 v = reinterpret_cast<const float4*>(x1)[idx];
        reinterpret_cast<__half2*>(g_Kh)[2*idx] =
            __halves2half2(__float2half_rn(k.x), __float2half_rn(k.y));
        reinterpret_cast<__half2*>(g_Kh)[2*idx+1] =
            __halves2half2(__float2half_rn(k.z), __float2half_rn(k.w));
        reinterpret_cast<__half2*>(g_Vh)[2*idx] =
            __halves2half2(__float2half_rn(v.x), __float2half_rn(v.y));
        reinterpret_cast<__half2*>(g_Vh)[2*idx+1] =
            __halves2half2(__float2half_rn(v.z), __float2half_rn(v.w));
    }

    unsigned lane  = idx & 31u;
    unsigned kt    = (idx >> 5) & 31u;
    unsigned warp  = (idx >> 10) & 3u;
    unsigned qtile = (idx >> 12) & 31u;
    unsigned bh    = idx >> 17;
    unsigned g = lane >> 2, c = lane & 3u;
    unsigned qrow = qtile * 64u + warp * 16u + g;
    unsigned gt = (bh * 2048u + qrow) * 2048u + 2u * c + kt * 64u;

    uint32_t keepbits = 0u;
    #pragma unroll
    for (int n = 0; n < 8; ++n) {
        unsigned gi = gt + (unsigned)(8 * n);
        unsigned y0 = threefry_keep_msb(gi);
        unsigned y1 = threefry_keep_msb(gi + 1u);
        unsigned y2 = threefry_keep_msb(gi + 16384u);
        unsigned y3 = threefry_keep_msb(gi + 16385u);
        keepbits = (keepbits >> 1) | (y0 & 0x80000000u);
        keepbits = (keepbits >> 1) | (y1 & 0x80000000u);
        keepbits = (keepbits >> 1) | (y2 & 0x80000000u);
        keepbits = (keepbits >> 1) | (y3 & 0x80000000u);
    }
    g_mask[idx] = keepbits;
}

__device__ __forceinline__ uint32_t packh2(__half a, __half b) {
    __half2 h = __halves2half2(a, b);
    return *reinterpret_cast<uint32_t*>(&h);
}
__device__ __forceinline__ void mma_f16(float c[4], const uint32_t a[4],
                                        uint32_t b0, uint32_t b1) {
    asm volatile(
        "mma.sync.aligned.m16n8k16.row.col.f32.f16.f16.f32 "
        "{%0,%1,%2,%3}, {%4,%5,%6,%7}, {%8,%9}, {%0,%1,%2,%3};\n"
        : "+f"(c[0]), "+f"(c[1]), "+f"(c[2]), "+f"(c[3])
        : "r"(a[0]), "r"(a[1]), "r"(a[2]), "r"(a[3]), "r"(b0), "r"(b1));
}
__device__ __forceinline__ void ldsm_x4(uint32_t& r0, uint32_t& r1,
                                        uint32_t& r2, uint32_t& r3, uint32_t addr) {
    asm volatile("ldmatrix.sync.aligned.m8n8.x4.shared.b16 {%0,%1,%2,%3}, [%4];"
                 : "=r"(r0), "=r"(r1), "=r"(r2), "=r"(r3) : "r"(addr));
}
__device__ __forceinline__ void ldsm_x4_t(uint32_t& r0, uint32_t& r1,
                                          uint32_t& r2, uint32_t& r3, uint32_t addr) {
    asm volatile("ldmatrix.sync.aligned.m8n8.x4.trans.shared.b16 {%0,%1,%2,%3}, [%4];"
                 : "=r"(r0), "=r"(r1), "=r"(r2), "=r"(r3) : "r"(addr));
}
__device__ __forceinline__ void cp_async16(uint32_t dst, const void* src) {
    asm volatile("cp.async.cg.shared.global [%0], [%1], 16;" :: "r"(dst), "l"(src));
}
__device__ __forceinline__ void cp_commit() { asm volatile("cp.async.commit_group;"); }
template <int N> __device__ __forceinline__ void cp_wait() {
    asm volatile("cp.async.wait_group %0;" :: "n"(N));
}

// stage a 128-row fp16 tile (2048 16B chunks)
__device__ __forceinline__ void stage128(uint32_t buf_b, const __half* src_base,
                                         int bh, int k0, int tid)
{
    const size_t base = (size_t)bh * (S_LEN * D_DIM) + (size_t)k0 * D_DIM;
    #pragma unroll
    for (int it = 0; it < 16; ++it) {
        int id  = tid + it * NT;        // 0..2047
        int row = id >> 4;              // 0..127
        int col = id & 15;
        cp_async16(buf_b + (uint32_t)(row * 272 + col * 16),
                   src_base + base + (size_t)row * D_DIM + col * 8);
    }
}

__global__ void __launch_bounds__(NT, 2)
attn_mma_kernel(const float* __restrict__ x1,
                const float* __restrict__ x2,
                const float* __restrict__ x3,
                float* __restrict__ out)
{
    extern __shared__ __half smh[];

    const int tid  = threadIdx.x;
    const int warp = tid >> 5;
    const int lane = tid & 31;
    const int g    = lane >> 2;
    const int c    = lane & 3;
    const int bh   = blockIdx.y;
    const int q0   = blockIdx.x * BM;
    const int qrow = q0 + warp * 16 + g;

    const float* Q = x1 + (size_t)bh * (S_LEN * D_DIM);
    const float* R = x2 + (size_t)bh * (S_LEN * D_DIM);
    float* O = out + (size_t)bh * (S_LEN * D_DIM);
    const float scl = (1.0f / x3[bh]) * 1.4426950408889634f;

    // mask row base (kt64-indexed words; this kernel consumes 2 per iteration)
    const uint32_t* mrow = g_mask
        + ((((size_t)bh * 32 + blockIdx.x) * 4 + warp) * 32) * 32 + lane;

    const uint32_t smem_u32 = (uint32_t)__cvta_generic_to_shared(smh);

    stage128(smem_u32 + OFF_K0, g_Kh, bh, 0, tid);
    cp_commit();

    // ---- Q fragments resident (fp16) ----
    uint32_t qh[8][4];
    #pragma unroll
    for (int t = 0; t < 8; ++t) {
        #pragma unroll
        for (int p = 0; p < 4; ++p) {
            int row = qrow + (p & 1) * 8;
            int col = 16 * t + (p >> 1) * 8 + 2 * c;
            float2 v = *reinterpret_cast<const float2*>(Q + (size_t)row * D_DIM + col);
            qh[t][p] = packh2(__float2half_rn(v.x), __float2half_rn(v.y));
        }
    }

    float oacc[16][4];
    #pragma unroll
    for (int i = 0; i < 16; ++i)
        #pragma unroll
        for (int j = 0; j < 4; ++j) oacc[i][j] = 0.0f;
    float m0 = -CUDART_INF_F, m1 = -CUDART_INF_F;
    float l0 = 0.0f, l1 = 0.0f;

    const int lr  = lane & 7;
    const int seg = lane >> 3;
    const uint32_t k_lane_off = (uint32_t)(lr * 272 + ((seg & 1) * 8 + (seg >> 1) * 16) * 2);
    const uint32_t v_lane_off = (uint32_t)(((seg & 1) * 8 + lr) * 272 + ((seg >> 1) * 8) * 2);
    const uint32_t kh_base0 = smem_u32 + k_lane_off;
    const uint32_t vh_base  = smem_u32 + (uint32_t)OFF_V + v_lane_off;

    for (int kt = 0; kt < S_LEN / BN; ++kt) {        // 16 iterations
        const uint32_t cur = (uint32_t)(kt & 1) * (uint32_t)KTILE_B;
        uint32_t kb0 = mrow[(2 * kt) * 32];
        uint32_t kb1 = mrow[(2 * kt + 1) * 32];

        __syncthreads();

        stage128(smem_u32 + OFF_V, g_Vh, bh, kt * BN, tid);
        cp_commit();
        if (kt + 1 < S_LEN / BN)
            stage128(smem_u32 + ((kt & 1) ? OFF_K0 : OFF_K1), g_Kh, bh, (kt + 1) * BN, tid);
        cp_commit();

        cp_wait<2>();     // K(kt) resident
        __syncthreads();

        const uint32_t kh_base = kh_base0 + cur;

        // ---- S = qh @ Kh^T over 128 cols: 16 n-groups ----
        float sacc[16][4];
        #pragma unroll
        for (int n = 0; n < 16; ++n) {
            sacc[n][0] = 0.0f; sacc[n][1] = 0.0f;
            sacc[n][2] = 0.0f; sacc[n][3] = 0.0f;
            const uint32_t rowoff = (uint32_t)(n * 8 * 272);
            #pragma unroll
            for (int dp = 0; dp < 4; ++dp) {
                uint32_t bh0, bh1, bh2, bh3;
                ldsm_x4(bh0, bh1, bh2, bh3, kh_base + rowoff + (uint32_t)(dp * 64));
                mma_f16(sacc[n], qh[2 * dp],     bh0, bh1);
                mma_f16(sacc[n], qh[2 * dp + 1], bh2, bh3);
            }
        }

        // ---- online softmax over 128 cols (exp2 domain) ----
        float mx0 = -CUDART_INF_F, mx1 = -CUDART_INF_F;
        #pragma unroll
        for (int n = 0; n < 16; ++n) {
            sacc[n][0] *= scl; sacc[n][1] *= scl;
            sacc[n][2] *= scl; sacc[n][3] *= scl;
            mx0 = fmaxf(mx0, fmaxf(sacc[n][0], sacc[n][1]));
            mx1 = fmaxf(mx1, fmaxf(sacc[n][2], sacc[n][3]));
        }
        mx0 = fmaxf(mx0, __shfl_xor_sync(0xffffffffu, mx0, 1));
        mx0 = fmaxf(mx0, __shfl_xor_sync(0xffffffffu, mx0, 2));
        mx1 = fmaxf(mx1, __shfl_xor_sync(0xffffffffu, mx1, 1));
        mx1 = fmaxf(mx1, __shfl_xor_sync(0xffffffffu, mx1, 2));
        float mn0 = fmaxf(m0, mx0), mn1 = fmaxf(m1, mx1);
        float sc0 = exp2f(m0 - mn0), sc1 = exp2f(m1 - mn1);
        m0 = mn0; m1 = mn1;
        float rs0 = 0.0f, rs1 = 0.0f;
        #pragma unroll
        for (int n = 0; n < 16; ++n) {
            sacc[n][0] = exp2f(sacc[n][0] - mn0);
            sacc[n][1] = exp2f(sacc[n][1] - mn0);
            sacc[n][2] = exp2f(sacc[n][2] - mn1);
            sacc[n][3] = exp2f(sacc[n][3] - mn1);
            rs0 += sacc[n][0] + sacc[n][1];
            rs1 += sacc[n][2] + sacc[n][3];
        }
        rs0 += __shfl_xor_sync(0xffffffffu, rs0, 1);
        rs0 += __shfl_xor_sync(0xffffffffu, rs0, 2);
        rs1 += __shfl_xor_sync(0xffffffffu, rs1, 1);
        rs1 += __shfl_xor_sync(0xffffffffu, rs1, 2);
        l0 = l0 * sc0 + rs0;
        l1 = l1 * sc1 + rs1;
        #pragma unroll
        for (int i = 0; i < 16; ++i) {
            oacc[i][0] *= sc0; oacc[i][1] *= sc0;
            oacc[i][2] *= sc1; oacc[i][3] *= sc1;
        }

        // ---- apply mask bits + pack P (n<8 -> kb0, n>=8 -> kb1) ----
        uint32_t pfr[16][2];
        #pragma unroll
        for (int n = 0; n < 16; ++n) {
            uint32_t kb = (n < 8) ? kb0 : kb1;
            int nb = (n & 7) * 4;
            float p00 = ((kb >> (nb + 0)) & 1u) ? sacc[n][0] : 0.0f;
            float p01 = ((kb >> (nb + 1)) & 1u) ? sacc[n][1] : 0.0f;
            float p10 = ((kb >> (nb + 2)) & 1u) ? sacc[n][2] : 0.0f;
            float p11 = ((kb >> (nb + 3)) & 1u) ? sacc[n][3] : 0.0f;
            pfr[n][0] = packh2(__float2half_rn(p00), __float2half_rn(p01));
            pfr[n][1] = packh2(__float2half_rn(p10), __float2half_rn(p11));
        }

        cp_wait<1>();     // V(kt) resident
        __syncthreads();

        // ---- O += P @ V  (K = 128 this tile: 8 kk groups) ----
        #pragma unroll
        for (int kk = 0; kk < 8; ++kk) {
            uint32_t a[4] = { pfr[2 * kk][0], pfr[2 * kk][1],
                              pfr[2 * kk + 1][0], pfr[2 * kk + 1][1] };
            const uint32_t kkoff = (uint32_t)(kk * 16 * 272);
            #pragma unroll
            for (int np = 0; np < 8; ++np) {
                uint32_t b0, b1, b2, b3;
                ldsm_x4_t(b0, b1, b2, b3, vh_base + kkoff + (uint32_t)(np * 32));
                mma_f16(oacc[2 * np],     a, b0, b1);
                mma_f16(oacc[2 * np + 1], a, b2, b3);
            }
        }
    }

    // ---- epilogue: out = 2*o/l + residual(x2) ----
    const float il0 = 2.0f / l0;
    const float il1 = 2.0f / l1;
    #pragma unroll
    for (int np = 0; np < 16; ++np) {
        int col = 8 * np + 2 * c;
        const float2 r0 = *reinterpret_cast<const float2*>(R + (size_t)qrow * D_DIM + col);
        const float2 r1 = *reinterpret_cast<const float2*>(R + (size_t)(qrow + 8) * D_DIM + col);
        float2 w0, w1;
        w0.x = fmaf(oacc[np][0], il0, r0.x);
        w0.y = fmaf(oacc[np][1], il0, r0.y);
        w1.x = fmaf(oacc[np][2], il1, r1.x);
        w1.y = fmaf(oacc[np][3], il1, r1.y);
        *reinterpret_cast<float2*>(O + (size_t)qrow * D_DIM + col) = w0;
        *reinterpret_cast<float2*>(O + (size_t)(qrow + 8) * D_DIM + col) = w1;
    }
}

extern "C" void kernel_launch(void* const* d_in, const int* in_sizes, int n_in,
                              void* d_out, int out_size) {
    const float* x1 = (const float*)d_in[0];
    const float* x2 = (const float*)d_in[1];
    const float* x3 = (const float*)d_in[2];
    float* out = (float*)d_out;
    (void)in_sizes; (void)n_in; (void)out_size;

    cudaFuncSetAttribute(attn_mma_kernel,
                         cudaFuncAttributeMaxDynamicSharedMemorySize, SMEM_BYTES);

    maskconv_kernel<<<NMASKW / 256, 256>>>(x1, x2);
    dim3 grid(S_LEN / BM, 32);
    attn_mma_kernel<<<grid, NT, SMEM_BYTES>>>(x1, x2, x3, out);
}

// round 16
// speedup vs baseline: 1.1047x; 1.1047x over previous
#include <cuda_runtime.h>
#include <cuda_fp16.h>
#include <math_constants.h>
#include <cstdint>

// Round 16: recombination of measured-good halves.
//  - maskconv_kernel (R15-proven): threefry keep-words + fp32->fp16 conversion
//    folded in; the 15us DRAM pass hides under the ~300us ALU wall.
//  - attn kernel = R14 verbatim (BN=64, 255us, issue ~50%): R15 showed BN=128
//    blows the register ceiling (issue 50->30%) — reverted.
// rel_err exactly 7.107e-4 (bit-identical R14 math + mask).

#define S_LEN 2048
#define D_DIM 128
#define BM 64
#define BN 64
#define NT 128
#define NELEM (2 * 16 * S_LEN * D_DIM)
#define NMASKW (1 << 22)

#define TILE_B 17408                    // one 64x128 fp16 tile (64*272 B)
#define OFF_K0 0
#define OFF_K1 TILE_B                   // 17408
#define OFF_V  (2 * TILE_B)             // 34816
#define SMEM_BYTES (3 * TILE_B)         // 52224 -> 2 CTAs/SM

__device__ __half g_Kh[NELEM];
__device__ __half g_Vh[NELEM];
__device__ uint32_t g_mask[NMASKW];

// ---------------- threefry (JAX partitionable, key=(0,42)), trimmed ----------------
__device__ __forceinline__ unsigned tf_rotl(unsigned x, int r) {
    return __funnelshift_l(x, x, r);
}
__device__ __forceinline__ unsigned threefry_keep_msb(unsigned g) {
    const unsigned ks1 = 42u;
    const unsigned ks2 = 0x1BD11BDAu ^ 42u;
    unsigned x0 = 0u;
    unsigned x1 = g + ks1;
#define TF_R(r)            { x0 += x1; x1 = tf_rotl(x1, (r)) ^ x0; }
#define TF_IR(ka, kb, r)   { x1 += (kb); x0 = x0 + (ka) + x1; x1 = tf_rotl(x1, (r)) ^ x0; }
    TF_R(13) TF_R(15) TF_R(26) TF_R(6)
    TF_IR(ks1, ks2 + 1u, 17) TF_R(29) TF_R(16) TF_R(24)
    TF_IR(ks2, 2u,       13) TF_R(15) TF_R(26) TF_R(6)
    TF_IR(0u,  ks1 + 3u, 17) TF_R(29) TF_R(16) TF_R(24)
    TF_IR(ks1, ks2 + 4u, 13) TF_R(15) TF_R(26) TF_R(6)
#undef TF_R
#undef TF_IR
    return ~((x0 + ks2) ^ (x1 + 5u));   // XNOR: MSB==1 iff KEEP
}

// ---------------- fused mask + convert kernel (R15-proven) ----------------
// mask word layout (BM=64 fragment indexing):
//   idx = ((((bh*32 + qtile)*4 + warp)*32 + kt)*32 + lane
// convert: first NELEM/4 threads each convert one float4 of K and V.
__global__ void __launch_bounds__(256)
maskconv_kernel(const float* __restrict__ x1, const float* __restrict__ x2)
{
    unsigned idx = blockIdx.x * 256u + threadIdx.x;

    // -- folded conversion (loads issue early; latency hides under threefry) --
    if (idx < (unsigned)(NELEM / 4)) {
        float4 k = reinterpret_cast<const float4*>(x2)[idx];
        float4 v = reinterpret_cast<const float4*>(x1)[idx];
        reinterpret_cast<__half2*>(g_Kh)[2*idx] =
            __halves2half2(__float2half_rn(k.x), __float2half_rn(k.y));
        reinterpret_cast<__half2*>(g_Kh)[2*idx+1] =
            __halves2half2(__float2half_rn(k.z), __float2half_rn(k.w));
        reinterpret_cast<__half2*>(g_Vh)[2*idx] =
            __halves2half2(__float2half_rn(v.x), __float2half_rn(v.y));
        reinterpret_cast<__half2*>(g_Vh)[2*idx+1] =
            __halves2half2(__float2half_rn(v.z), __float2half_rn(v.w));
    }

    unsigned lane  = idx & 31u;
    unsigned kt    = (idx >> 5) & 31u;
    unsigned warp  = (idx >> 10) & 3u;
    unsigned qtile = (idx >> 12) & 31u;
    unsigned bh    = idx >> 17;
    unsigned g = lane >> 2, c = lane & 3u;
    unsigned qrow = qtile * 64u + warp * 16u + g;
    unsigned gt = (bh * 2048u + qrow) * 2048u + 2u * c + kt * 64u;

    uint32_t keepbits = 0u;
    #pragma unroll
    for (int n = 0; n < 8; ++n) {
        unsigned gi = gt + (unsigned)(8 * n);
        unsigned y0 = threefry_keep_msb(gi);
        unsigned y1 = threefry_keep_msb(gi + 1u);
        unsigned y2 = threefry_keep_msb(gi + 16384u);
        unsigned y3 = threefry_keep_msb(gi + 16385u);
        keepbits = (keepbits >> 1) | (y0 & 0x80000000u);
        keepbits = (keepbits >> 1) | (y1 & 0x80000000u);
        keepbits = (keepbits >> 1) | (y2 & 0x80000000u);
        keepbits = (keepbits >> 1) | (y3 & 0x80000000u);
    }
    g_mask[idx] = keepbits;
}

__device__ __forceinline__ uint32_t packh2(__half a, __half b) {
    __half2 h = __halves2half2(a, b);
    return *reinterpret_cast<uint32_t*>(&h);
}
__device__ __forceinline__ void mma_f16(float c[4], const uint32_t a[4],
                                        uint32_t b0, uint32_t b1) {
    asm volatile(
        "mma.sync.aligned.m16n8k16.row.col.f32.f16.f16.f32 "
        "{%0,%1,%2,%3}, {%4,%5,%6,%7}, {%8,%9}, {%0,%1,%2,%3};\n"
        : "+f"(c[0]), "+f"(c[1]), "+f"(c[2]), "+f"(c[3])
        : "r"(a[0]), "r"(a[1]), "r"(a[2]), "r"(a[3]), "r"(b0), "r"(b1));
}
__device__ __forceinline__ void ldsm_x4(uint32_t& r0, uint32_t& r1,
                                        uint32_t& r2, uint32_t& r3, uint32_t addr) {
    asm volatile("ldmatrix.sync.aligned.m8n8.x4.shared.b16 {%0,%1,%2,%3}, [%4];"
                 : "=r"(r0), "=r"(r1), "=r"(r2), "=r"(r3) : "r"(addr));
}
__device__ __forceinline__ void ldsm_x4_t(uint32_t& r0, uint32_t& r1,
                                          uint32_t& r2, uint32_t& r3, uint32_t addr) {
    asm volatile("ldmatrix.sync.aligned.m8n8.x4.trans.shared.b16 {%0,%1,%2,%3}, [%4];"
                 : "=r"(r0), "=r"(r1), "=r"(r2), "=r"(r3) : "r"(addr));
}
__device__ __forceinline__ void cp_async16(uint32_t dst, const void* src) {
    asm volatile("cp.async.cg.shared.global [%0], [%1], 16;" :: "r"(dst), "l"(src));
}
__device__ __forceinline__ void cp_commit() { asm volatile("cp.async.commit_group;"); }
template <int N> __device__ __forceinline__ void cp_wait() {
    asm volatile("cp.async.wait_group %0;" :: "n"(N));
}

__device__ __forceinline__ void stage_k(uint32_t buf_b, int bh, int k0, int tid)
{
    const size_t kbase = (size_t)bh * (S_LEN * D_DIM) + (size_t)k0 * D_DIM;
    #pragma unroll
    for (int it = 0; it < 8; ++it) {
        int id  = tid + it * NT;        // 0..1023
        int row = id >> 4;
        int col = id & 15;
        cp_async16(buf_b + (uint32_t)(row * 272 + col * 16),
                   g_Kh + kbase + (size_t)row * D_DIM + col * 8);
    }
}
__device__ __forceinline__ void stage_v(uint32_t vbuf_b, int bh, int k0, int tid)
{
    const size_t kbase = (size_t)bh * (S_LEN * D_DIM) + (size_t)k0 * D_DIM;
    #pragma unroll
    for (int it = 0; it < 8; ++it) {
        int id  = tid + it * NT;
        int row = id >> 4;
        int col = id & 15;
        cp_async16(vbuf_b + (uint32_t)(row * 272 + col * 16),
                   g_Vh + kbase + (size_t)row * D_DIM + col * 8);
    }
}

__global__ void __launch_bounds__(NT, 2)
attn_mma_kernel(const float* __restrict__ x1,
                const float* __restrict__ x2,
                const float* __restrict__ x3,
                float* __restrict__ out)
{
    extern __shared__ __half smh[];

    const int tid  = threadIdx.x;
    const int warp = tid >> 5;
    const int lane = tid & 31;
    const int g    = lane >> 2;
    const int c    = lane & 3;
    const int bh   = blockIdx.y;
    const int q0   = blockIdx.x * BM;
    const int qrow = q0 + warp * 16 + g;

    const float* Q = x1 + (size_t)bh * (S_LEN * D_DIM);
    const float* R = x2 + (size_t)bh * (S_LEN * D_DIM);
    float* O = out + (size_t)bh * (S_LEN * D_DIM);
    const float scl = (1.0f / x3[bh]) * 1.4426950408889634f;

    const uint32_t* mrow = g_mask
        + ((((size_t)bh * 32 + blockIdx.x) * 4 + warp) * 32) * 32 + lane;

    const uint32_t smem_u32 = (uint32_t)__cvta_generic_to_shared(smh);

    stage_k(smem_u32 + OFF_K0, bh, 0, tid);
    cp_commit();

    // ---- Q fragments resident (fp16 hi only) ----
    uint32_t qh[8][4];
    #pragma unroll
    for (int t = 0; t < 8; ++t) {
        #pragma unroll
        for (int p = 0; p < 4; ++p) {
            int row = qrow + (p & 1) * 8;
            int col = 16 * t + (p >> 1) * 8 + 2 * c;
            float2 v = *reinterpret_cast<const float2*>(Q + (size_t)row * D_DIM + col);
            qh[t][p] = packh2(__float2half_rn(v.x), __float2half_rn(v.y));
        }
    }

    float oacc[16][4];
    #pragma unroll
    for (int i = 0; i < 16; ++i)
        #pragma unroll
        for (int j = 0; j < 4; ++j) oacc[i][j] = 0.0f;
    float m0 = -CUDART_INF_F, m1 = -CUDART_INF_F;
    float l0 = 0.0f, l1 = 0.0f;

    const int lr  = lane & 7;
    const int seg = lane >> 3;
    const uint32_t k_lane_off = (uint32_t)(lr * 272 + ((seg & 1) * 8 + (seg >> 1) * 16) * 2);
    const uint32_t v_lane_off = (uint32_t)(((seg & 1) * 8 + lr) * 272 + ((seg >> 1) * 8) * 2);
    const uint32_t kh_base0 = smem_u32 + k_lane_off;
    const uint32_t vh_base  = smem_u32 + (uint32_t)OFF_V + v_lane_off;

    for (int kt = 0; kt < 32; ++kt) {
        const uint32_t cur = (uint32_t)(kt & 1) * (uint32_t)TILE_B;
        uint32_t keepbits = mrow[kt * 32];

        __syncthreads();

        stage_v(smem_u32 + OFF_V, bh, kt * BN, tid);
        cp_commit();
        if (kt + 1 < 32)
            stage_k(smem_u32 + ((kt & 1) ? OFF_K0 : OFF_K1), bh, (kt + 1) * BN, tid);
        cp_commit();

        cp_wait<2>();     // K(kt) resident
        __syncthreads();

        const uint32_t kh_base = kh_base0 + cur;

        // ---- S = qh @ Kh^T : 1 pass, 2 MMAs per (n, dp) ----
        float sacc[8][4];
        #pragma unroll
        for (int n = 0; n < 8; ++n) {
            sacc[n][0] = 0.0f; sacc[n][1] = 0.0f;
            sacc[n][2] = 0.0f; sacc[n][3] = 0.0f;
            const uint32_t rowoff = (uint32_t)(n * 8 * 272);
            #pragma unroll
            for (int dp = 0; dp < 4; ++dp) {
                uint32_t bh0, bh1, bh2, bh3;
                ldsm_x4(bh0, bh1, bh2, bh3, kh_base + rowoff + (uint32_t)(dp * 64));
                mma_f16(sacc[n], qh[2 * dp],     bh0, bh1);
                mma_f16(sacc[n], qh[2 * dp + 1], bh2, bh3);
            }
        }

        // ---- online softmax (exp2 domain) ----
        float mx0 = -CUDART_INF_F, mx1 = -CUDART_INF_F;
        #pragma unroll
        for (int n = 0; n < 8; ++n) {
            sacc[n][0] *= scl; sacc[n][1] *= scl;
            sacc[n][2] *= scl; sacc[n][3] *= scl;
            mx0 = fmaxf(mx0, fmaxf(sacc[n][0], sacc[n][1]));
            mx1 = fmaxf(mx1, fmaxf(sacc[n][2], sacc[n][3]));
        }
        mx0 = fmaxf(mx0, __shfl_xor_sync(0xffffffffu, mx0, 1));
        mx0 = fmaxf(mx0, __shfl_xor_sync(0xffffffffu, mx0, 2));
        mx1 = fmaxf(mx1, __shfl_xor_sync(0xffffffffu, mx1, 1));
        mx1 = fmaxf(mx1, __shfl_xor_sync(0xffffffffu, mx1, 2));
        float mn0 = fmaxf(m0, mx0), mn1 = fmaxf(m1, mx1);
        float sc0 = exp2f(m0 - mn0), sc1 = exp2f(m1 - mn1);
        m0 = mn0; m1 = mn1;
        float rs0 = 0.0f, rs1 = 0.0f;
        #pragma unroll
        for (int n = 0; n < 8; ++n) {
            sacc[n][0] = exp2f(sacc[n][0] - mn0);
            sacc[n][1] = exp2f(sacc[n][1] - mn0);
            sacc[n][2] = exp2f(sacc[n][2] - mn1);
            sacc[n][3] = exp2f(sacc[n][3] - mn1);
            rs0 += sacc[n][0] + sacc[n][1];
            rs1 += sacc[n][2] + sacc[n][3];
        }
        rs0 += __shfl_xor_sync(0xffffffffu, rs0, 1);
        rs0 += __shfl_xor_sync(0xffffffffu, rs0, 2);
        rs1 += __shfl_xor_sync(0xffffffffu, rs1, 1);
        rs1 += __shfl_xor_sync(0xffffffffu, rs1, 2);
        l0 = l0 * sc0 + rs0;
        l1 = l1 * sc1 + rs1;
        #pragma unroll
        for (int i = 0; i < 16; ++i) {
            oacc[i][0] *= sc0; oacc[i][1] *= sc0;
            oacc[i][2] *= sc1; oacc[i][3] *= sc1;
        }

        // ---- apply mask bits + pack P ----
        uint32_t pfr[8][2];
        #pragma unroll
        for (int n = 0; n < 8; ++n) {
            float p00 = ((keepbits >> (4 * n + 0)) & 1u) ? sacc[n][0] : 0.0f;
            float p01 = ((keepbits >> (4 * n + 1)) & 1u) ? sacc[n][1] : 0.0f;
            float p10 = ((keepbits >> (4 * n + 2)) & 1u) ? sacc[n][2] : 0.0f;
            float p11 = ((keepbits >> (4 * n + 3)) & 1u) ? sacc[n][3] : 0.0f;
            pfr[n][0] = packh2(__float2half_rn(p00), __float2half_rn(p01));
            pfr[n][1] = packh2(__float2half_rn(p10), __float2half_rn(p11));
        }

        cp_wait<1>();     // V(kt) resident
        __syncthreads();

        // ---- O += P @ V ----
        #pragma unroll
        for (int kk = 0; kk < 4; ++kk) {
            uint32_t a[4] = { pfr[2 * kk][0], pfr[2 * kk][1],
                              pfr[2 * kk + 1][0], pfr[2 * kk + 1][1] };
            const uint32_t kkoff = (uint32_t)(kk * 16 * 272);
            #pragma unroll
            for (int np = 0; np < 8; ++np) {
                uint32_t b0, b1, b2, b3;
                ldsm_x4_t(b0, b1, b2, b3, vh_base + kkoff + (uint32_t)(np * 32));
                mma_f16(oacc[2 * np],     a, b0, b1);
                mma_f16(oacc[2 * np + 1], a, b2, b3);
            }
        }
    }

    // ---- epilogue: out = 2*o/l + residual(x2) ----
    const float il0 = 2.0f / l0;
    const float il1 = 2.0f / l1;
    #pragma unroll
    for (int np = 0; np < 16; ++np) {
        int col = 8 * np + 2 * c;
        const float2 r0 = *reinterpret_cast<const float2*>(R + (size_t)qrow * D_DIM + col);
        const float2 r1 = *reinterpret_cast<const float2*>(R + (size_t)(qrow + 8) * D_DIM + col);
        float2 w0, w1;
        w0.x = fmaf(oacc[np][0], il0, r0.x);
        w0.y = fmaf(oacc[np][1], il0, r0.y);
        w1.x = fmaf(oacc[np][2], il1, r1.x);
        w1.y = fmaf(oacc[np][3], il1, r1.y);
        *reinterpret_cast<float2*>(O + (size_t)qrow * D_DIM + col) = w0;
        *reinterpret_cast<float2*>(O + (size_t)(qrow + 8) * D_DIM + col) = w1;
    }
}

extern "C" void kernel_launch(void* const* d_in, const int* in_sizes, int n_in,
                              void* d_out, int out_size) {
    const float* x1 = (const float*)d_in[0];
    const float* x2 = (const float*)d_in[1];
    const float* x3 = (const float*)d_in[2];
    float* out = (float*)d_out;
    (void)in_sizes; (void)n_in; (void)out_size;

    cudaFuncSetAttribute(attn_mma_kernel,
                         cudaFuncAttributeMaxDynamicSharedMemorySize, SMEM_BYTES);

    maskconv_kernel<<<NMASKW / 256, 256>>>(x1, x2);
    dim3 grid(S_LEN / BM, 32);
    attn_mma_kernel<<<grid, NT, SMEM_BYTES>>>(x1, x2, x3, out);
}